// round 6
// baseline (speedup 1.0000x reference)
#include <cuda_runtime.h>
#include <math.h>

// Problem constants
#define B 2
#define C 256
#define H 64
#define Wd 64
#define CMID 64
#define CENC 100
#define HH 128
#define WW 128
#define KUP 25

// Scratch (device globals — no allocation allowed)
__device__ float g_W1[B * CMID * H * Wd];   // 2 MB   conv1x1+bn+relu result
__device__ float g_W2[B * CENC * H * Wd];   // 3.1 MB conv3x3+bn result
__device__ float g_Wn[B * KUP * HH * WW];   // 3.1 MB softmaxed kernels (b,k,y,x)

// ---------------------------------------------------------------------------
// Kernel A: 1x1 conv (256 -> 64) + BN + ReLU.  GEMM over pixels.
// grid = B*H = 128 blocks, 256 threads = 64 w-pixels x 4 m-groups of 16.
// ---------------------------------------------------------------------------
__global__ void __launch_bounds__(256) conv1x1_bn_relu(
    const float* __restrict__ X, const float* __restrict__ cw,
    const float* __restrict__ gamma, const float* __restrict__ beta,
    const float* __restrict__ mean, const float* __restrict__ var)
{
    __shared__ __align__(16) float sw[128 * 64];   // 32 KB: [c_local][m]
    const int b = blockIdx.x >> 6;
    const int h = blockIdx.x & 63;
    const int tid = threadIdx.x;
    const int wcol = tid & 63;
    const int mg = tid >> 6;          // 0..3, handles m in [mg*16, mg*16+16)

    float acc[16];
#pragma unroll
    for (int j = 0; j < 16; ++j) acc[j] = 0.f;

    const float* Xbase = X + (size_t)b * C * H * Wd + h * Wd + wcol;

    for (int half = 0; half < 2; ++half) {
        for (int i = tid; i < 128 * 64; i += 256) {
            int c_local = i >> 6, m = i & 63;
            sw[i] = cw[m * 256 + half * 128 + c_local];
        }
        __syncthreads();
#pragma unroll 4
        for (int c = 0; c < 128; ++c) {
            float xv = Xbase[(size_t)(half * 128 + c) * (H * Wd)];
            const float4* wp = (const float4*)&sw[c * 64 + mg * 16];
#pragma unroll
            for (int j = 0; j < 4; ++j) {
                float4 w4 = wp[j];
                acc[j * 4 + 0] = fmaf(xv, w4.x, acc[j * 4 + 0]);
                acc[j * 4 + 1] = fmaf(xv, w4.y, acc[j * 4 + 1]);
                acc[j * 4 + 2] = fmaf(xv, w4.z, acc[j * 4 + 2]);
                acc[j * 4 + 3] = fmaf(xv, w4.w, acc[j * 4 + 3]);
            }
        }
        __syncthreads();
    }

#pragma unroll
    for (int j = 0; j < 16; ++j) {
        int m = mg * 16 + j;
        float s = gamma[m] * rsqrtf(var[m] + 1e-5f);
        float o = fmaxf(fmaf(acc[j], s, beta[m] - mean[m] * s), 0.f);
        g_W1[(((size_t)b * CMID + m) * H + h) * Wd + wcol] = o;
    }
}

// ---------------------------------------------------------------------------
// Kernel B: 3x3 conv (64 -> 100, pad=1) + BN (no relu).
// grid = (16 tiles, B, 5 oc-groups), 256 threads = 16x16 pixel tile.
// Each thread accumulates 20 output channels; weights in smem read as float4.
// ---------------------------------------------------------------------------
#define OCB 20
#define ICB 16
__global__ void __launch_bounds__(256) conv3x3_bn(
    const float* __restrict__ ew,
    const float* __restrict__ gamma, const float* __restrict__ beta,
    const float* __restrict__ mean, const float* __restrict__ var)
{
    __shared__ __align__(16) float xs[ICB * 18 * 18];   // 20.7 KB
    __shared__ __align__(16) float ws[ICB * 9 * OCB];   // 11.5 KB

    const int tile = blockIdx.x;
    const int b = blockIdx.y;
    const int ocg = blockIdx.z;
    const int ty0 = (tile >> 2) * 16, tx0 = (tile & 3) * 16;
    const int tid = threadIdx.x;
    const int px = tid & 15, py = tid >> 4;

    float acc[OCB];
#pragma unroll
    for (int j = 0; j < OCB; ++j) acc[j] = 0.f;

    for (int icb = 0; icb < CMID; icb += ICB) {
        for (int i = tid; i < ICB * 324; i += 256) {
            int ic = i / 324, pos = i % 324;
            int r = pos / 18, c = pos % 18;
            int gr = ty0 + r - 1, gc = tx0 + c - 1;
            float v = 0.f;
            if ((unsigned)gr < 64u && (unsigned)gc < 64u)
                v = g_W1[(((size_t)b * CMID + icb + ic) * H + gr) * Wd + gc];
            xs[i] = v;
        }
        for (int i = tid; i < ICB * 9 * OCB; i += 256) {
            int ic = i / (9 * OCB), rem = i % (9 * OCB);
            int tap = rem / OCB, l = rem % OCB;
            ws[i] = ew[((size_t)(ocg * OCB + l) * CMID + icb + ic) * 9 + tap];
        }
        __syncthreads();
#pragma unroll 1
        for (int ic = 0; ic < ICB; ++ic) {
#pragma unroll
            for (int ky = 0; ky < 3; ++ky)
#pragma unroll
            for (int kx = 0; kx < 3; ++kx) {
                float xv = xs[ic * 324 + (py + ky) * 18 + (px + kx)];
                const float4* wp =
                    (const float4*)&ws[(ic * 9 + ky * 3 + kx) * OCB];
#pragma unroll
                for (int j = 0; j < 5; ++j) {
                    float4 w4 = wp[j];
                    acc[j * 4 + 0] = fmaf(xv, w4.x, acc[j * 4 + 0]);
                    acc[j * 4 + 1] = fmaf(xv, w4.y, acc[j * 4 + 1]);
                    acc[j * 4 + 2] = fmaf(xv, w4.z, acc[j * 4 + 2]);
                    acc[j * 4 + 3] = fmaf(xv, w4.w, acc[j * 4 + 3]);
                }
            }
        }
        __syncthreads();
    }

    const int h = ty0 + py, w = tx0 + px;
#pragma unroll
    for (int j = 0; j < OCB; ++j) {
        int oc = ocg * OCB + j;
        float s = gamma[oc] * rsqrtf(var[oc] + 1e-5f);
        g_W2[(((size_t)b * CENC + oc) * H + h) * Wd + w] =
            fmaf(acc[j], s, beta[oc] - mean[oc] * s);
    }
}

// ---------------------------------------------------------------------------
// Kernel C: pixel_shuffle(r=2) + clamp + pow + softmax over 25 taps.
// One thread per hi-res pixel. grid = 2*128*128/256 = 128 blocks.
// ---------------------------------------------------------------------------
__global__ void __launch_bounds__(256) shuffle_pow_softmax(
    const float* __restrict__ power_p)
{
    const int idx = blockIdx.x * 256 + threadIdx.x;   // 0 .. 32767
    const int b = idx >> 14;
    const int pix = idx & 16383;
    const int y = pix >> 7, x = pix & 127;
    const int yi = y >> 1, xi = x >> 1;
    const int off = (y & 1) * 2 + (x & 1);

    const float p = fmaxf(power_p[0], 1e-5f);

    float v[25];
    float mx = -1e30f;
#pragma unroll
    for (int k = 0; k < 25; ++k) {
        float w = g_W2[(((size_t)b * CENC + k * 4 + off) * H + yi) * Wd + xi];
        w = fmaxf(w, 1e-5f);
        w = powf(w, p);
        v[k] = w;
        mx = fmaxf(mx, w);
    }
    float s = 0.f;
#pragma unroll
    for (int k = 0; k < 25; ++k) { v[k] = expf(v[k] - mx); s += v[k]; }
    float inv = 1.f / s;
#pragma unroll
    for (int k = 0; k < 25; ++k)
        g_Wn[(((size_t)b * KUP + k) * HH + y) * WW + x] = v[k] * inv;
}

// ---------------------------------------------------------------------------
// Kernel D: CARAFE aggregate on the low-res grid.
// out[b,c,2yi+sy,2xi+sx] = sum_{ki,kj} W[...] * X[b,c,yi+ki-2,xi+kj-2]
// grid = (64 low-res 8x8 tiles, 4 ch-groups of 64, B).
// 256 threads = 64 low-res pixels x 4 ch-lanes; W (100 vals) in registers,
// X tile (12x12 x 64ch) in smem; 1 LDS per 4 FMA.
// ---------------------------------------------------------------------------
__global__ void __launch_bounds__(256) carafe_agg(
    const float* __restrict__ X, float* __restrict__ out)
{
    __shared__ float xs[64 * 144];   // 36.9 KB
    const int b = blockIdx.z;
    const int cg = blockIdx.y;        // channels [cg*64, cg*64+64)
    const int tile = blockIdx.x;
    const int ty0 = (tile >> 3) * 8, tx0 = (tile & 7) * 8;
    const int tid = threadIdx.x;
    const int pix = tid & 63, lane = tid >> 6;
    const int pyi = pix >> 3, pxi = pix & 7;
    const int yi = ty0 + pyi, xi = tx0 + pxi;

    // Load X tile with halo 2 (zero-padded), 64 channels.
    for (int i = tid; i < 64 * 144; i += 256) {
        int ch = i / 144, pos = i % 144;
        int r = pos / 12, c = pos % 12;
        int gr = ty0 + r - 2, gc = tx0 + c - 2;
        float v = 0.f;
        if ((unsigned)gr < 64u && (unsigned)gc < 64u)
            v = X[(((size_t)b * C + cg * 64 + ch) * H + gr) * Wd + gc];
        xs[i] = v;
    }

    // Load the 4 subpixels' 25 weights into registers.
    float wreg[4][25];
#pragma unroll
    for (int s = 0; s < 4; ++s) {
        int yy = 2 * yi + (s >> 1), xx = 2 * xi + (s & 1);
#pragma unroll
        for (int k = 0; k < 25; ++k)
            wreg[s][k] = g_Wn[(((size_t)b * KUP + k) * HH + yy) * WW + xx];
    }
    __syncthreads();

    const size_t obase = (((size_t)b * C + cg * 64) * HH) * WW;
    const int y0 = 2 * yi, x0 = 2 * xi;

#pragma unroll 1
    for (int j = 0; j < 16; ++j) {
        const int ch = lane * 16 + j;       // warp-uniform
        float a0 = 0.f, a1 = 0.f, a2 = 0.f, a3 = 0.f;
#pragma unroll
        for (int ki = 0; ki < 5; ++ki)
#pragma unroll
        for (int kj = 0; kj < 5; ++kj) {
            float xv = xs[ch * 144 + (pyi + ki) * 12 + (pxi + kj)];
            const int k = ki * 5 + kj;
            a0 = fmaf(wreg[0][k], xv, a0);
            a1 = fmaf(wreg[1][k], xv, a1);
            a2 = fmaf(wreg[2][k], xv, a2);
            a3 = fmaf(wreg[3][k], xv, a3);
        }
        float* op = out + obase + ((size_t)ch * HH + y0) * WW + x0;
        *(float2*)op = make_float2(a0, a1);
        *(float2*)(op + WW) = make_float2(a2, a3);
    }
}

// ---------------------------------------------------------------------------
extern "C" void kernel_launch(void* const* d_in, const int* in_sizes, int n_in,
                              void* d_out, int out_size) {
    const float* X          = (const float*)d_in[0];
    const float* comp_w     = (const float*)d_in[1];
    const float* comp_gamma = (const float*)d_in[2];
    const float* comp_beta  = (const float*)d_in[3];
    const float* comp_mean  = (const float*)d_in[4];
    const float* comp_var   = (const float*)d_in[5];
    const float* enc_w      = (const float*)d_in[6];
    const float* enc_gamma  = (const float*)d_in[7];
    const float* enc_beta   = (const float*)d_in[8];
    const float* enc_mean   = (const float*)d_in[9];
    const float* enc_var    = (const float*)d_in[10];
    const float* power_p    = (const float*)d_in[11];
    float* out = (float*)d_out;

    conv1x1_bn_relu<<<B * H, 256>>>(X, comp_w, comp_gamma, comp_beta,
                                    comp_mean, comp_var);
    conv3x3_bn<<<dim3(16, B, 5), 256>>>(enc_w, enc_gamma, enc_beta,
                                        enc_mean, enc_var);
    shuffle_pow_softmax<<<(B * HH * WW) / 256, 256>>>(power_p);
    carafe_agg<<<dim3(64, 4, B), 256>>>(X, out);
}

// round 7
// speedup vs baseline: 1.0751x; 1.0751x over previous
#include <cuda_runtime.h>
#include <math.h>

// Problem constants
#define B 2
#define C 256
#define H 64
#define Wd 64
#define CMID 64
#define CENC 100
#define HH 128
#define WW 128
#define KUP 25

typedef unsigned long long u64;

// Scratch (device globals — no allocation allowed)
__device__ __align__(16) float g_W1[B * CMID * H * Wd];   // conv1x1+bn+relu
__device__ __align__(16) float g_W2[B * CENC * H * Wd];   // conv3x3+bn
__device__ __align__(16) float g_Wn[B * KUP * HH * WW];   // softmaxed kernels

// ---- packed f32x2 helpers (sm_100+) --------------------------------------
__device__ __forceinline__ u64 splat2(float x) {
    u64 r; asm("mov.b64 %0, {%1, %1};" : "=l"(r) : "f"(x)); return r;
}
__device__ __forceinline__ u64 fma2(u64 a, u64 b, u64 c) {
    u64 d; asm("fma.rn.f32x2 %0, %1, %2, %3;" : "=l"(d)
               : "l"(a), "l"(b), "l"(c)); return d;
}
__device__ __forceinline__ float2 unpack2(u64 v) {
    float2 f; asm("mov.b64 {%0, %1}, %2;" : "=f"(f.x), "=f"(f.y) : "l"(v));
    return f;
}

// ---------------------------------------------------------------------------
// Kernel A: 1x1 conv (256 -> 64) + BN + ReLU.
// grid = (B*H, 2 col-halves), 256 threads = 32 w-cols x 8 oc-groups of 8.
// ---------------------------------------------------------------------------
__global__ void __launch_bounds__(256) conv1x1_bn_relu(
    const float* __restrict__ X, const float* __restrict__ cw,
    const float* __restrict__ gamma, const float* __restrict__ beta,
    const float* __restrict__ mean, const float* __restrict__ var)
{
    __shared__ __align__(16) float sw[128 * 64];   // 32 KB: [c_local][m]
    const int b = blockIdx.x >> 6;
    const int h = blockIdx.x & 63;
    const int tid = threadIdx.x;
    const int wcol = (blockIdx.y << 5) + (tid & 31);
    const int mg = tid >> 5;          // 0..7, oc in [mg*8, mg*8+8)

    u64 acc[4] = {0ull, 0ull, 0ull, 0ull};

    const float* Xbase = X + (size_t)b * C * H * Wd + h * Wd + wcol;

    for (int half = 0; half < 2; ++half) {
        for (int i = tid; i < 128 * 64; i += 256) {
            int c_local = i >> 6, m = i & 63;
            sw[i] = cw[m * 256 + half * 128 + c_local];
        }
        __syncthreads();
#pragma unroll 4
        for (int c = 0; c < 128; ++c) {
            float xv = Xbase[(size_t)(half * 128 + c) * (H * Wd)];
            u64 xx = splat2(xv);
            const ulonglong2* wp =
                (const ulonglong2*)&sw[c * 64 + mg * 8];
            ulonglong2 q0 = wp[0];
            ulonglong2 q1 = wp[1];
            acc[0] = fma2(xx, q0.x, acc[0]);
            acc[1] = fma2(xx, q0.y, acc[1]);
            acc[2] = fma2(xx, q1.x, acc[2]);
            acc[3] = fma2(xx, q1.y, acc[3]);
        }
        __syncthreads();
    }

#pragma unroll
    for (int j = 0; j < 4; ++j) {
        float2 v = unpack2(acc[j]);
        int m0 = mg * 8 + 2 * j;
        float s0 = gamma[m0] * rsqrtf(var[m0] + 1e-5f);
        float s1 = gamma[m0 + 1] * rsqrtf(var[m0 + 1] + 1e-5f);
        float o0 = fmaxf(fmaf(v.x, s0, beta[m0] - mean[m0] * s0), 0.f);
        float o1 = fmaxf(fmaf(v.y, s1, beta[m0 + 1] - mean[m0 + 1] * s1), 0.f);
        g_W1[(((size_t)b * CMID + m0) * H + h) * Wd + wcol] = o0;
        g_W1[(((size_t)b * CMID + m0 + 1) * H + h) * Wd + wcol] = o1;
    }
}

// ---------------------------------------------------------------------------
// Kernel B: 3x3 conv (64 -> 100, pad=1) + BN (no relu).
// grid = (16 tiles, B, 10 oc-groups of 10), 256 threads = 16x16 pixel tile.
// Each thread accumulates 10 output channels as 5 f32x2 pairs.
// ---------------------------------------------------------------------------
#define ICB 16
__global__ void __launch_bounds__(256) conv3x3_bn(
    const float* __restrict__ ew,
    const float* __restrict__ gamma, const float* __restrict__ beta,
    const float* __restrict__ mean, const float* __restrict__ var)
{
    __shared__ __align__(16) float xs[ICB * 324];        // 20.7 KB
    __shared__ __align__(16) float ws[ICB * 9 * 12];     // 6.9 KB (10 used, pad 12)

    const int tile = blockIdx.x;
    const int b = blockIdx.y;
    const int ocg = blockIdx.z;                // 10 oc per group
    const int ty0 = (tile >> 2) * 16, tx0 = (tile & 3) * 16;
    const int tid = threadIdx.x;
    const int px = tid & 15, py = tid >> 4;

    u64 acc[5] = {0ull, 0ull, 0ull, 0ull, 0ull};

    for (int icb = 0; icb < CMID; icb += ICB) {
        for (int i = tid; i < ICB * 324; i += 256) {
            int ic = i / 324, pos = i % 324;
            int r = pos / 18, c = pos % 18;
            int gr = ty0 + r - 1, gc = tx0 + c - 1;
            float v = 0.f;
            if ((unsigned)gr < 64u && (unsigned)gc < 64u)
                v = g_W1[(((size_t)b * CMID + icb + ic) * H + gr) * Wd + gc];
            xs[i] = v;
        }
        for (int i = tid; i < ICB * 90; i += 256) {
            int ic = i / 90, rem = i % 90;
            int tap = rem / 10, l = rem % 10;
            ws[(ic * 9 + tap) * 12 + l] =
                ew[((size_t)(ocg * 10 + l) * CMID + icb + ic) * 9 + tap];
        }
        __syncthreads();
#pragma unroll 1
        for (int ic = 0; ic < ICB; ++ic) {
#pragma unroll
            for (int ky = 0; ky < 3; ++ky)
#pragma unroll
            for (int kx = 0; kx < 3; ++kx) {
                float xv = xs[ic * 324 + (py + ky) * 18 + (px + kx)];
                u64 xx = splat2(xv);
                const float* wrow = &ws[(ic * 9 + ky * 3 + kx) * 12];
                ulonglong2 qa = *(const ulonglong2*)wrow;
                ulonglong2 qb = *(const ulonglong2*)(wrow + 4);
                u64 qc = *(const u64*)(wrow + 8);
                acc[0] = fma2(xx, qa.x, acc[0]);
                acc[1] = fma2(xx, qa.y, acc[1]);
                acc[2] = fma2(xx, qb.x, acc[2]);
                acc[3] = fma2(xx, qb.y, acc[3]);
                acc[4] = fma2(xx, qc, acc[4]);
            }
        }
        __syncthreads();
    }

    const int h = ty0 + py, w = tx0 + px;
#pragma unroll
    for (int j = 0; j < 5; ++j) {
        float2 v = unpack2(acc[j]);
        int oc = ocg * 10 + 2 * j;
        float s0 = gamma[oc] * rsqrtf(var[oc] + 1e-5f);
        float s1 = gamma[oc + 1] * rsqrtf(var[oc + 1] + 1e-5f);
        g_W2[(((size_t)b * CENC + oc) * H + h) * Wd + w] =
            fmaf(v.x, s0, beta[oc] - mean[oc] * s0);
        g_W2[(((size_t)b * CENC + oc + 1) * H + h) * Wd + w] =
            fmaf(v.y, s1, beta[oc + 1] - mean[oc + 1] * s1);
    }
}

// ---------------------------------------------------------------------------
// Kernel C: pixel_shuffle(r=2) + clamp + pow + softmax over 25 taps.
// ---------------------------------------------------------------------------
__global__ void __launch_bounds__(256) shuffle_pow_softmax(
    const float* __restrict__ power_p)
{
    const int idx = blockIdx.x * 256 + threadIdx.x;   // 0 .. 32767
    const int b = idx >> 14;
    const int pix = idx & 16383;
    const int y = pix >> 7, x = pix & 127;
    const int yi = y >> 1, xi = x >> 1;
    const int off = (y & 1) * 2 + (x & 1);

    const float p = fmaxf(power_p[0], 1e-5f);

    float v[25];
    float mx = -1e30f;
#pragma unroll
    for (int k = 0; k < 25; ++k) {
        float w = g_W2[(((size_t)b * CENC + k * 4 + off) * H + yi) * Wd + xi];
        w = fmaxf(w, 1e-5f);
        w = __powf(w, p);
        v[k] = w;
        mx = fmaxf(mx, w);
    }
    float s = 0.f;
#pragma unroll
    for (int k = 0; k < 25; ++k) { v[k] = __expf(v[k] - mx); s += v[k]; }
    float inv = 1.f / s;
#pragma unroll
    for (int k = 0; k < 25; ++k)
        g_Wn[(((size_t)b * KUP + k) * HH + y) * WW + x] = v[k] * inv;
}

// ---------------------------------------------------------------------------
// Kernel D: CARAFE aggregate on the low-res grid.
// out[b,c,2yi+sy,2xi+sx] = sum_{ki,kj} W * X[b,c,yi+ki-2,xi+kj-2]
// Tile = 2x32 low-res pixels so each warp's 32 lanes span one full x-row of
// the haloed smem tile (stride 36, warp-uniform row base) -> conflict-free
// LDS. Weights for the 4 subpixels live in registers as 2 f32x2 packs per
// tap (adjacent-x pairs loaded as single LDG.64). Channels processed in two
// 32-channel smem phases (stays under 48 KB static smem).
// grid = (64 tiles, 4 ch-groups of 64, B), 256 thr = 64 px x 4 ch-lanes.
// ---------------------------------------------------------------------------
__global__ void __launch_bounds__(256, 2) carafe_agg(
    const float* __restrict__ X, float* __restrict__ out)
{
    __shared__ float xs[32 * 216];   // 27.65 KB: 32 ch x 6 rows x 36 cols
    const int b = blockIdx.z;
    const int cg = blockIdx.y;                 // channels [cg*64, cg*64+64)
    const int tile = blockIdx.x;
    const int ty0 = (tile >> 1) * 2, tx0 = (tile & 1) * 32;
    const int tid = threadIdx.x;
    const int pix = tid & 63, lane = tid >> 6;
    const int pyi = pix >> 5, pxi = pix & 31;  // pyi warp-uniform
    const int yi = ty0 + pyi, xi = tx0 + pxi;
    const int y0 = 2 * yi, x0 = 2 * xi;

    // The 4 subpixels' 25 weights, packed as f32x2 (adjacent x): persist
    // across both channel phases.
    u64 w01[25], w23[25];
#pragma unroll
    for (int k = 0; k < 25; ++k) {
        const float* p = g_Wn + (((size_t)b * KUP + k) * HH + y0) * WW + x0;
        w01[k] = *(const u64*)p;          // (sy=0,sx=0),(sy=0,sx=1)
        w23[k] = *(const u64*)(p + WW);   // (sy=1,sx=0),(sy=1,sx=1)
    }

    const size_t cbase = (size_t)b * C + cg * 64;

    for (int h2 = 0; h2 < 2; ++h2) {
        __syncthreads();
        // Load 32-channel X tile with halo 2 (zero-padded): 6 rows x 36 cols.
        for (int i = tid; i < 32 * 216; i += 256) {
            int ch = i / 216, pos = i % 216;
            int r = pos / 36, c = pos % 36;
            int gr = ty0 + r - 2, gc = tx0 + c - 2;
            float v = 0.f;
            if ((unsigned)gr < 64u && (unsigned)gc < 64u)
                v = X[((cbase + h2 * 32 + ch) * H + gr) * Wd + gc];
            xs[i] = v;
        }
        __syncthreads();

#pragma unroll 1
        for (int j = 0; j < 8; ++j) {
            const int chl = lane * 8 + j;            // warp-uniform
            const float* xp = &xs[chl * 216 + pyi * 36 + pxi];
            u64 a01 = 0ull, a23 = 0ull;
#pragma unroll
            for (int ki = 0; ki < 5; ++ki)
#pragma unroll
            for (int kj = 0; kj < 5; ++kj) {
                u64 xx = splat2(xp[ki * 36 + kj]);
                const int k = ki * 5 + kj;
                a01 = fma2(xx, w01[k], a01);
                a23 = fma2(xx, w23[k], a23);
            }
            float* op = out +
                ((cbase + h2 * 32 + chl) * HH + y0) * WW + x0;
            *(u64*)op = a01;
            *(u64*)(op + WW) = a23;
        }
    }
}

// ---------------------------------------------------------------------------
extern "C" void kernel_launch(void* const* d_in, const int* in_sizes, int n_in,
                              void* d_out, int out_size) {
    const float* X          = (const float*)d_in[0];
    const float* comp_w     = (const float*)d_in[1];
    const float* comp_gamma = (const float*)d_in[2];
    const float* comp_beta  = (const float*)d_in[3];
    const float* comp_mean  = (const float*)d_in[4];
    const float* comp_var   = (const float*)d_in[5];
    const float* enc_w      = (const float*)d_in[6];
    const float* enc_gamma  = (const float*)d_in[7];
    const float* enc_beta   = (const float*)d_in[8];
    const float* enc_mean   = (const float*)d_in[9];
    const float* enc_var    = (const float*)d_in[10];
    const float* power_p    = (const float*)d_in[11];
    float* out = (float*)d_out;

    conv1x1_bn_relu<<<dim3(B * H, 2), 256>>>(X, comp_w, comp_gamma, comp_beta,
                                             comp_mean, comp_var);
    conv3x3_bn<<<dim3(16, B, 10), 256>>>(enc_w, enc_gamma, enc_beta,
                                         enc_mean, enc_var);
    shuffle_pow_softmax<<<(B * HH * WW) / 256, 256>>>(power_p);
    carafe_agg<<<dim3(64, 4, B), 256>>>(X, out);
}

// round 9
// speedup vs baseline: 1.2817x; 1.1921x over previous
#include <cuda_runtime.h>
#include <math.h>

// Problem constants
#define B 2
#define C 256
#define H 64
#define Wd 64
#define CMID 64
#define CENC 100
#define HH 128
#define WW 128
#define KUP 25

typedef unsigned long long u64;

// Scratch (device globals — no allocation allowed)
__device__ __align__(16) float g_W1[B * CMID * H * Wd];    // conv1x1+bn+relu
__device__ __align__(16) float g_W2a[B * CENC * H * Wd];   // conv3x3 ic half 0 (s*a+t)
__device__ __align__(16) float g_W2b[B * CENC * H * Wd];   // conv3x3 ic half 1 (s*b)
__device__ __align__(16) float g_Wn[B * KUP * HH * WW];    // softmaxed kernels

// ---- packed f32x2 helpers (sm_100+) --------------------------------------
__device__ __forceinline__ u64 splat2(float x) {
    u64 r; asm("mov.b64 %0, {%1, %1};" : "=l"(r) : "f"(x)); return r;
}
__device__ __forceinline__ u64 fma2(u64 a, u64 b, u64 c) {
    u64 d; asm("fma.rn.f32x2 %0, %1, %2, %3;" : "=l"(d)
               : "l"(a), "l"(b), "l"(c)); return d;
}
__device__ __forceinline__ float2 unpack2(u64 v) {
    float2 f; asm("mov.b64 {%0, %1}, %2;" : "=f"(f.x), "=f"(f.y) : "l"(v));
    return f;
}

// ---------------------------------------------------------------------------
// Kernel A: 1x1 conv (256 -> 64) + BN + ReLU.
// grid = (B*H, 2 col-halves), 256 threads = 32 w-cols x 8 oc-groups of 8.
// ---------------------------------------------------------------------------
__global__ void __launch_bounds__(256) conv1x1_bn_relu(
    const float* __restrict__ X, const float* __restrict__ cw,
    const float* __restrict__ gamma, const float* __restrict__ beta,
    const float* __restrict__ mean, const float* __restrict__ var)
{
    __shared__ __align__(16) float sw[128 * 64];   // 32 KB: [c_local][m]
    const int b = blockIdx.x >> 6;
    const int h = blockIdx.x & 63;
    const int tid = threadIdx.x;
    const int wcol = (blockIdx.y << 5) + (tid & 31);
    const int mg = tid >> 5;          // 0..7, oc in [mg*8, mg*8+8)

    u64 acc[4] = {0ull, 0ull, 0ull, 0ull};

    const float* Xbase = X + (size_t)b * C * H * Wd + h * Wd + wcol;

    for (int half = 0; half < 2; ++half) {
        for (int i = tid; i < 128 * 64; i += 256) {
            int c_local = i >> 6, m = i & 63;
            sw[i] = cw[m * 256 + half * 128 + c_local];
        }
        __syncthreads();
#pragma unroll 4
        for (int c = 0; c < 128; ++c) {
            float xv = Xbase[(size_t)(half * 128 + c) * (H * Wd)];
            u64 xx = splat2(xv);
            const ulonglong2* wp =
                (const ulonglong2*)&sw[c * 64 + mg * 8];
            ulonglong2 q0 = wp[0];
            ulonglong2 q1 = wp[1];
            acc[0] = fma2(xx, q0.x, acc[0]);
            acc[1] = fma2(xx, q0.y, acc[1]);
            acc[2] = fma2(xx, q1.x, acc[2]);
            acc[3] = fma2(xx, q1.y, acc[3]);
        }
        __syncthreads();
    }

#pragma unroll
    for (int j = 0; j < 4; ++j) {
        float2 v = unpack2(acc[j]);
        int m0 = mg * 8 + 2 * j;
        float s0 = gamma[m0] * rsqrtf(var[m0] + 1e-5f);
        float s1 = gamma[m0 + 1] * rsqrtf(var[m0 + 1] + 1e-5f);
        float o0 = fmaxf(fmaf(v.x, s0, beta[m0] - mean[m0] * s0), 0.f);
        float o1 = fmaxf(fmaf(v.y, s1, beta[m0 + 1] - mean[m0 + 1] * s1), 0.f);
        g_W1[(((size_t)b * CMID + m0) * H + h) * Wd + wcol] = o0;
        g_W1[(((size_t)b * CMID + m0 + 1) * H + h) * Wd + wcol] = o1;
    }
}

// ---------------------------------------------------------------------------
// Kernel B: 3x3 conv (64 -> 100, pad=1), BN folded into the two ic-halves:
//   half 0 writes s*partial + t,   half 1 writes s*partial
// so that (g_W2a + g_W2b) == full BN output. Softmax kernel sums them.
// grid = (16 tiles, B, 20 = 10 oc-groups x 2 ic-halves), 128 threads.
// Each thread: 2 pixels (py, py+8) x 10 oc (5 f32x2 pairs each).
// ---------------------------------------------------------------------------
#define ICB 16
__global__ void __launch_bounds__(128) conv3x3_bn(
    const float* __restrict__ ew,
    const float* __restrict__ gamma, const float* __restrict__ beta,
    const float* __restrict__ mean, const float* __restrict__ var)
{
    __shared__ __align__(16) float xs[ICB * 324];        // 20.7 KB
    __shared__ __align__(16) float ws[ICB * 9 * 12];     // 6.9 KB (10 used, pad 12)

    const int tile = blockIdx.x;
    const int b = blockIdx.y;
    const int ocg = blockIdx.z >> 1;           // 10 oc per group
    const int ih  = blockIdx.z & 1;            // ic half
    const int ty0 = (tile >> 2) * 16, tx0 = (tile & 3) * 16;
    const int tid = threadIdx.x;
    const int px = tid & 15, py = tid >> 4;    // py 0..7; second pixel py+8

    u64 acc0[5] = {0ull, 0ull, 0ull, 0ull, 0ull};
    u64 acc1[5] = {0ull, 0ull, 0ull, 0ull, 0ull};

    for (int ib = 0; ib < 2; ++ib) {
        const int icb = ih * 32 + ib * ICB;
        for (int i = tid; i < ICB * 324; i += 128) {
            int ic = i / 324, pos = i % 324;
            int r = pos / 18, c = pos % 18;
            int gr = ty0 + r - 1, gc = tx0 + c - 1;
            float v = 0.f;
            if ((unsigned)gr < 64u && (unsigned)gc < 64u)
                v = g_W1[(((size_t)b * CMID + icb + ic) * H + gr) * Wd + gc];
            xs[i] = v;
        }
        for (int i = tid; i < ICB * 90; i += 128) {
            int ic = i / 90, rem = i % 90;
            int tap = rem / 10, l = rem % 10;
            ws[(ic * 9 + tap) * 12 + l] =
                ew[((size_t)(ocg * 10 + l) * CMID + icb + ic) * 9 + tap];
        }
        __syncthreads();
#pragma unroll 1
        for (int ic = 0; ic < ICB; ++ic) {
#pragma unroll
            for (int ky = 0; ky < 3; ++ky)
#pragma unroll
            for (int kx = 0; kx < 3; ++kx) {
                float xv0 = xs[ic * 324 + (py + ky) * 18 + (px + kx)];
                float xv1 = xs[ic * 324 + (py + 8 + ky) * 18 + (px + kx)];
                u64 xx0 = splat2(xv0);
                u64 xx1 = splat2(xv1);
                const float* wrow = &ws[(ic * 9 + ky * 3 + kx) * 12];
                ulonglong2 qa = *(const ulonglong2*)wrow;
                ulonglong2 qb = *(const ulonglong2*)(wrow + 4);
                u64 qc = *(const u64*)(wrow + 8);
                acc0[0] = fma2(xx0, qa.x, acc0[0]);
                acc0[1] = fma2(xx0, qa.y, acc0[1]);
                acc0[2] = fma2(xx0, qb.x, acc0[2]);
                acc0[3] = fma2(xx0, qb.y, acc0[3]);
                acc0[4] = fma2(xx0, qc,   acc0[4]);
                acc1[0] = fma2(xx1, qa.x, acc1[0]);
                acc1[1] = fma2(xx1, qa.y, acc1[1]);
                acc1[2] = fma2(xx1, qb.x, acc1[2]);
                acc1[3] = fma2(xx1, qb.y, acc1[3]);
                acc1[4] = fma2(xx1, qc,   acc1[4]);
            }
        }
        __syncthreads();
    }

    float* dst = ih ? g_W2b : g_W2a;
    const int h0 = ty0 + py, h1 = h0 + 8, w = tx0 + px;
#pragma unroll
    for (int j = 0; j < 5; ++j) {
        float2 v0 = unpack2(acc0[j]);
        float2 v1 = unpack2(acc1[j]);
        int oc = ocg * 10 + 2 * j;
        float s0 = gamma[oc] * rsqrtf(var[oc] + 1e-5f);
        float s1 = gamma[oc + 1] * rsqrtf(var[oc + 1] + 1e-5f);
        float t0 = ih ? 0.f : (beta[oc] - mean[oc] * s0);
        float t1 = ih ? 0.f : (beta[oc + 1] - mean[oc + 1] * s1);
        dst[(((size_t)b * CENC + oc) * H + h0) * Wd + w] = fmaf(v0.x, s0, t0);
        dst[(((size_t)b * CENC + oc + 1) * H + h0) * Wd + w] = fmaf(v0.y, s1, t1);
        dst[(((size_t)b * CENC + oc) * H + h1) * Wd + w] = fmaf(v1.x, s0, t0);
        dst[(((size_t)b * CENC + oc + 1) * H + h1) * Wd + w] = fmaf(v1.y, s1, t1);
    }
}

// ---------------------------------------------------------------------------
// Kernel C: sum halves + pixel_shuffle(r=2) + clamp + pow + softmax (25 taps).
// ---------------------------------------------------------------------------
__global__ void __launch_bounds__(256) shuffle_pow_softmax(
    const float* __restrict__ power_p)
{
    const int idx = blockIdx.x * 256 + threadIdx.x;   // 0 .. 32767
    const int b = idx >> 14;
    const int pix = idx & 16383;
    const int y = pix >> 7, x = pix & 127;
    const int yi = y >> 1, xi = x >> 1;
    const int off = (y & 1) * 2 + (x & 1);

    const float p = fmaxf(power_p[0], 1e-5f);

    float v[25];
    float mx = -1e30f;
#pragma unroll
    for (int k = 0; k < 25; ++k) {
        size_t o = (((size_t)b * CENC + k * 4 + off) * H + yi) * Wd + xi;
        float w = g_W2a[o] + g_W2b[o];
        w = fmaxf(w, 1e-5f);
        w = __powf(w, p);
        v[k] = w;
        mx = fmaxf(mx, w);
    }
    float s = 0.f;
#pragma unroll
    for (int k = 0; k < 25; ++k) { v[k] = __expf(v[k] - mx); s += v[k]; }
    float inv = 1.f / s;
#pragma unroll
    for (int k = 0; k < 25; ++k)
        g_Wn[(((size_t)b * KUP + k) * HH + y) * WW + x] = v[k] * inv;
}

// ---------------------------------------------------------------------------
// Kernel D: CARAFE aggregate on the low-res grid.
// out[b,c,2yi+sy,2xi+sx] = sum_{ki,kj} W * X[b,c,yi+ki-2,xi+kj-2]
// Tile = 2x32 low-res pixels; warp lanes span one full x-row of the haloed
// smem tile (stride 36, warp-uniform row base) -> conflict-free LDS.
// Threads: 64 pix x 2 sy x 2 ch-lanes; each thread holds ONE subpixel-row's
// 25 weights as f32x2 packs (50 regs, no spills) and processes 16 channels
// (2 at a time, 2 independent FMA chains). X in 32-ch smem phases.
// grid = (64 tiles, 4 ch-groups of 64, B).
// ---------------------------------------------------------------------------
__global__ void __launch_bounds__(256) carafe_agg(
    const float* __restrict__ X, float* __restrict__ out)
{
    __shared__ float xs[32 * 216];   // 27.65 KB: 32 ch x 6 rows x 36 cols
    const int b = blockIdx.z;
    const int cg = blockIdx.y;                 // channels [cg*64, cg*64+64)
    const int tile = blockIdx.x;
    const int ty0 = (tile >> 1) * 2, tx0 = (tile & 1) * 32;
    const int tid = threadIdx.x;
    const int pix = tid & 63;
    const int sy = (tid >> 6) & 1;
    const int chl = tid >> 7;                  // 0..1
    const int pyi = pix >> 5, pxi = pix & 31;  // pyi warp-uniform
    const int yi = ty0 + pyi, xi = tx0 + pxi;
    const int y0 = 2 * yi, x0 = 2 * xi;

    // This thread's subpixel-row weights: (sx=0,sx=1) pairs for row y0+sy.
    u64 wk[25];
#pragma unroll
    for (int k = 0; k < 25; ++k)
        wk[k] = *(const u64*)(g_Wn +
                 (((size_t)b * KUP + k) * HH + y0 + sy) * WW + x0);

    const size_t cbase = (size_t)b * C + cg * 64;

    for (int h2 = 0; h2 < 2; ++h2) {
        __syncthreads();
        // Load 32-channel X tile with halo 2 (zero-padded): 6 rows x 36 cols.
        for (int i = tid; i < 32 * 216; i += 256) {
            int ch = i / 216, pos = i % 216;
            int r = pos / 36, c = pos % 36;
            int gr = ty0 + r - 2, gc = tx0 + c - 2;
            float v = 0.f;
            if ((unsigned)gr < 64u && (unsigned)gc < 64u)
                v = X[((cbase + h2 * 32 + ch) * H + gr) * Wd + gc];
            xs[i] = v;
        }
        __syncthreads();

#pragma unroll 1
        for (int j = 0; j < 8; ++j) {
            const int ch0 = chl * 16 + 2 * j;        // warp-uniform
            const float* xp0 = &xs[ch0 * 216 + pyi * 36 + pxi];
            const float* xp1 = xp0 + 216;
            u64 a0 = 0ull, a1 = 0ull;
#pragma unroll
            for (int ki = 0; ki < 5; ++ki)
#pragma unroll
            for (int kj = 0; kj < 5; ++kj) {
                const int k = ki * 5 + kj;
                u64 x0v = splat2(xp0[ki * 36 + kj]);
                u64 x1v = splat2(xp1[ki * 36 + kj]);
                a0 = fma2(x0v, wk[k], a0);
                a1 = fma2(x1v, wk[k], a1);
            }
            float* op = out +
                ((cbase + h2 * 32 + ch0) * HH + y0 + sy) * WW + x0;
            *(u64*)op = a0;
            *(u64*)(op + (size_t)HH * WW) = a1;
        }
    }
}

// ---------------------------------------------------------------------------
extern "C" void kernel_launch(void* const* d_in, const int* in_sizes, int n_in,
                              void* d_out, int out_size) {
    const float* X          = (const float*)d_in[0];
    const float* comp_w     = (const float*)d_in[1];
    const float* comp_gamma = (const float*)d_in[2];
    const float* comp_beta  = (const float*)d_in[3];
    const float* comp_mean  = (const float*)d_in[4];
    const float* comp_var   = (const float*)d_in[5];
    const float* enc_w      = (const float*)d_in[6];
    const float* enc_gamma  = (const float*)d_in[7];
    const float* enc_beta   = (const float*)d_in[8];
    const float* enc_mean   = (const float*)d_in[9];
    const float* enc_var    = (const float*)d_in[10];
    const float* power_p    = (const float*)d_in[11];
    float* out = (float*)d_out;

    conv1x1_bn_relu<<<dim3(B * H, 2), 256>>>(X, comp_w, comp_gamma, comp_beta,
                                             comp_mean, comp_var);
    conv3x3_bn<<<dim3(16, B, 20), 128>>>(enc_w, enc_gamma, enc_beta,
                                         enc_mean, enc_var);
    shuffle_pow_softmax<<<(B * HH * WW) / 256, 256>>>(power_p);
    carafe_agg<<<dim3(64, 4, B), 256>>>(X, out);
}